// round 1
// baseline (speedup 1.0000x reference)
#include <cuda_runtime.h>
#include <math.h>

#define BB 16
#define NN 8192
#define KK 128
#define MM (NN + KK)          // 8320
#define FG_THRESH 0.5f

// scratch: bestk (bits 0..7) | fg flag (bit 8), per (b, m)
__device__ int g_combo[BB * MM];

// ---------------------------------------------------------------------------
// Kernel 1: per-roi IoU argmax over K gt boxes; writes combo scratch and the
// focal inside/outside weights (which live in ORIGINAL roi order).
// ---------------------------------------------------------------------------
__global__ void __launch_bounds__(256)
ptl_iou_kernel(const float* __restrict__ rois_in,  // (B,N,5)
               const float* __restrict__ gt_in,    // (B,K,5)
               float* __restrict__ out_inw,        // (B,M,4)
               float* __restrict__ out_outw)       // (B,M,4)
{
    const int b = blockIdx.y;
    __shared__ float4 sbox[KK];
    __shared__ float  sarea[KK];

    const float* gtb = gt_in + (size_t)b * KK * 5;
    for (int k = threadIdx.x; k < KK; k += blockDim.x) {
        float x1 = gtb[k * 5 + 0];
        float y1 = gtb[k * 5 + 1];
        float x2 = gtb[k * 5 + 2];
        float y2 = gtb[k * 5 + 3];
        float gw = x2 - x1 + 1.0f;
        float gh = y2 - y1 + 1.0f;
        float area = gw * gh;
        if (gw == 1.0f && gh == 1.0f)
            area = __int_as_float(0x7f800000);   // +inf -> ov = inter/inf = 0
        sbox[k]  = make_float4(x1, y1, x2, y2);
        sarea[k] = area;
    }
    __syncthreads();

    const int m = blockIdx.x * blockDim.x + threadIdx.x;
    if (m >= MM) return;

    float x1, y1, x2, y2;
    if (m < NN) {
        const float* r = rois_in + ((size_t)b * NN + m) * 5;
        x1 = r[1]; y1 = r[2]; x2 = r[3]; y2 = r[4];
    } else {
        const float* g = gtb + (size_t)(m - NN) * 5;
        x1 = g[0]; y1 = g[1]; x2 = g[2]; y2 = g[3];
    }

    const float aw = x2 - x1 + 1.0f;
    const float ah = y2 - y1 + 1.0f;
    const float areaA = aw * ah;
    const bool  an_zero = (aw == 1.0f) && (ah == 1.0f);

    float best = -1e30f;
    int bestk = 0;

#pragma unroll 8
    for (int k = 0; k < KK; k++) {
        float4 g4 = sbox[k];
        float iw = fminf(x2, g4.z) - fmaxf(x1, g4.x) + 1.0f;
        float ih = fminf(y2, g4.w) - fmaxf(y1, g4.y) + 1.0f;
        iw = fmaxf(iw, 0.0f);
        ih = fmaxf(ih, 0.0f);
        float inter = iw * ih;
        float ov = inter / (areaA + sarea[k] - inter);
        if (ov > best) { best = ov; bestk = k; }
    }

    if (an_zero) { best = -1.0f; bestk = 0; }

    const bool fg = (best >= FG_THRESH);
    g_combo[b * MM + m] = bestk | (fg ? 256 : 0);

    float focal = fg ? (1.0f - best) * (1.0f - best) : 0.0f;
    float ow = (focal > 0.0f) ? 1.0f : 0.0f;
    const size_t o = ((size_t)b * MM + m) * 4;
    out_inw[o + 0] = focal; out_inw[o + 1] = focal;
    out_inw[o + 2] = focal; out_inw[o + 3] = focal;
    out_outw[o + 0] = ow; out_outw[o + 1] = ow;
    out_outw[o + 2] = ow; out_outw[o + 3] = ow;
}

// ---------------------------------------------------------------------------
// Kernel 2: per-batch stable fg/bg partition (exclusive scan of fg flags)
// and scatter of rois_batch / labels_batch / bbox_targets.
// One block per batch, 1024 threads.
// ---------------------------------------------------------------------------
__global__ void __launch_bounds__(1024)
ptl_scatter_kernel(const float* __restrict__ rois_in,  // (B,N,5)
                   const float* __restrict__ gt_in,    // (B,K,5)
                   float* __restrict__ out_rois,       // (B,M,5)
                   float* __restrict__ out_lab,        // (B,M)
                   float* __restrict__ out_tgt)        // (B,M,4)
{
    const int b = blockIdx.x;
    const int tid = threadIdx.x;
    const int lane = tid & 31;
    const int warp = tid >> 5;

    __shared__ float sgt[KK * 5];
    __shared__ int s_wsum[32];
    __shared__ int s_totfg;
    __shared__ int s_carry;
    __shared__ int s_blocksum;

    const float* gtb = gt_in + (size_t)b * KK * 5;
    for (int i = tid; i < KK * 5; i += 1024) sgt[i] = gtb[i];
    if (tid == 0) { s_totfg = 0; s_carry = 0; }
    __syncthreads();

    // total fg count for this batch
    int cnt = 0;
    for (int m = tid; m < MM; m += 1024)
        cnt += (g_combo[b * MM + m] >> 8) & 1;
#pragma unroll
    for (int off = 16; off; off >>= 1)
        cnt += __shfl_down_sync(0xffffffffu, cnt, off);
    if (lane == 0) atomicAdd(&s_totfg, cnt);
    __syncthreads();
    const int totfg = s_totfg;

    for (int base = 0; base < MM; base += 1024) {
        const int m = base + tid;
        int combo = 0, flag = 0;
        if (m < MM) {
            combo = g_combo[b * MM + m];
            flag = (combo >> 8) & 1;
        }

        const unsigned bal = __ballot_sync(0xffffffffu, flag != 0);
        const int wpre = __popc(bal & ((1u << lane) - 1u));
        if (lane == 0) s_wsum[warp] = __popc(bal);
        __syncthreads();

        if (warp == 0) {
            int v = s_wsum[lane];
            int inc = v;
#pragma unroll
            for (int off = 1; off < 32; off <<= 1) {
                int t = __shfl_up_sync(0xffffffffu, inc, off);
                if (lane >= off) inc += t;
            }
            s_wsum[lane] = inc - v;               // exclusive warp prefix
            if (lane == 31) s_blocksum = inc;     // chunk total
        }
        __syncthreads();

        const int prefix = s_carry + s_wsum[warp] + wpre;  // #fg in [0, m)

        if (m < MM) {
            const int bestk = combo & 255;
            const int dest = flag ? prefix : (totfg + (m - prefix));

            float x1, y1, x2, y2;
            if (m < NN) {
                const float* r = rois_in + ((size_t)b * NN + m) * 5;
                x1 = r[1]; y1 = r[2]; x2 = r[3]; y2 = r[4];
            } else {
                const float* g = &sgt[(m - NN) * 5];
                x1 = g[0]; y1 = g[1]; x2 = g[2]; y2 = g[3];
            }

            const size_t ro = ((size_t)b * MM + dest) * 5;
            out_rois[ro + 0] = (float)b;
            out_rois[ro + 1] = x1;
            out_rois[ro + 2] = y1;
            out_rois[ro + 3] = x2;
            out_rois[ro + 4] = y2;

            const float cls = sgt[bestk * 5 + 4];
            const float lab = flag ? cls : 0.0f;
            out_lab[(size_t)b * MM + dest] = lab;

            float t0 = 0.0f, t1 = 0.0f, t2 = 0.0f, t3 = 0.0f;
            if (lab > 0.0f) {
                const float gx1 = sgt[bestk * 5 + 0];
                const float gy1 = sgt[bestk * 5 + 1];
                const float gx2 = sgt[bestk * 5 + 2];
                const float gy2 = sgt[bestk * 5 + 3];
                const float ew = x2 - x1 + 1.0f;
                const float eh = y2 - y1 + 1.0f;
                const float ecx = x1 + 0.5f * ew;
                const float ecy = y1 + 0.5f * eh;
                const float gw = gx2 - gx1 + 1.0f;
                const float gh = gy2 - gy1 + 1.0f;
                const float gcx = gx1 + 0.5f * gw;
                const float gcy = gy1 + 0.5f * gh;
                t0 = ((gcx - ecx) / ew) / 0.1f;
                t1 = ((gcy - ecy) / eh) / 0.1f;
                t2 = logf(gw / ew) / 0.2f;
                t3 = logf(gh / eh) / 0.2f;
            }
            const size_t to = ((size_t)b * MM + dest) * 4;
            out_tgt[to + 0] = t0;
            out_tgt[to + 1] = t1;
            out_tgt[to + 2] = t2;
            out_tgt[to + 3] = t3;
        }
        __syncthreads();
        if (tid == 0) s_carry += s_blocksum;
        __syncthreads();
    }
}

// ---------------------------------------------------------------------------
extern "C" void kernel_launch(void* const* d_in, const int* in_sizes, int n_in,
                              void* d_out, int out_size)
{
    const float* rois = (const float*)d_in[0];   // (16, 8192, 5) f32
    const float* gt   = (const float*)d_in[1];   // (16, 128, 5) f32
    float* out = (float*)d_out;

    // outputs concatenated in reference tuple order
    float* out_rois = out;                                   // B*M*5
    float* out_lab  = out_rois + (size_t)BB * MM * 5;        // B*M
    float* out_tgt  = out_lab  + (size_t)BB * MM;            // B*M*4
    float* out_inw  = out_tgt  + (size_t)BB * MM * 4;        // B*M*4
    float* out_outw = out_inw  + (size_t)BB * MM * 4;        // B*M*4

    dim3 g1((MM + 255) / 256, BB);
    ptl_iou_kernel<<<g1, 256>>>(rois, gt, out_inw, out_outw);
    ptl_scatter_kernel<<<BB, 1024>>>(rois, gt, out_rois, out_lab, out_tgt);
}